// round 1
// baseline (speedup 1.0000x reference)
#include <cuda_runtime.h>
#include <cstdint>
#include <cstddef>

// Problem dims (fixed by the dataset)
#define S_DIM 8192
#define E_DIM 4096
#define H_DIM 32
#define D_DIM 128   // E/H

// ---------------------------------------------------------------------------
// Scratch (static __device__ arrays: no allocation allowed in kernel_launch)
// ---------------------------------------------------------------------------
__device__ float g_Q [(size_t)S_DIM * E_DIM];   // Q = x@Wq.T + bq        (128 MiB)
__device__ float g_Kc[(size_t)S_DIM * D_DIM];   // Kc[s,d] = k[s,d,0]     (4 MiB)
__device__ float g_Wt[(size_t)S_DIM * H_DIM];   // softmax weights        (1 MiB)

// ---------------------------------------------------------------------------
// SGEMM: C[M,N] = X[M,K] @ W.T + bias, with W row n at W + n*wRowStride
// and bias[n*biasStride]. All dims here are exact multiples of the tile, so
// no bounds checks are needed (M=8192, N in {4096,128}, K=4096).
// 128x128 block tile, BK=8, 8x8 per-thread microtile, 256 threads.
// ---------------------------------------------------------------------------
#define BM 128
#define BN 128
#define BK 8

__global__ __launch_bounds__(256)
void sgemm_tn_bias(const float* __restrict__ X,
                   const float* __restrict__ W,
                   const float* __restrict__ bias,
                   float* __restrict__ C,
                   int N, int K, int wRowStride, int biasStride)
{
    __shared__ float As[BK][BM + 4];
    __shared__ float Bs[BK][BN + 4];

    const int tid = threadIdx.x;
    const int m0 = blockIdx.y * BM;
    const int n0 = blockIdx.x * BN;

    // global->smem load mapping: each thread loads one float4 of X and one of W
    const int lr = tid >> 1;           // 0..127 : row within tile
    const int lc = (tid & 1) << 2;     // 0 or 4 : k offset within BK

    const float* Xp = X + (size_t)(m0 + lr) * K + lc;
    const float* Wp = W + (size_t)(n0 + lr) * wRowStride + lc;

    // compute mapping: 16x16 thread grid, each thread owns rows {mA..mA+3, mA+64..}
    const int tx = tid & 15;
    const int ty = tid >> 4;
    const int mA = ty << 2;
    const int nA = tx << 2;

    float acc[8][8];
#pragma unroll
    for (int i = 0; i < 8; ++i)
#pragma unroll
        for (int j = 0; j < 8; ++j) acc[i][j] = 0.f;

    for (int k0 = 0; k0 < K; k0 += BK) {
        float4 xa = *(const float4*)(Xp + k0);
        float4 wa = *(const float4*)(Wp + k0);
        __syncthreads();   // previous iter's compute done before smem overwrite
        As[lc + 0][lr] = xa.x; As[lc + 1][lr] = xa.y;
        As[lc + 2][lr] = xa.z; As[lc + 3][lr] = xa.w;
        Bs[lc + 0][lr] = wa.x; Bs[lc + 1][lr] = wa.y;
        Bs[lc + 2][lr] = wa.z; Bs[lc + 3][lr] = wa.w;
        __syncthreads();
#pragma unroll
        for (int k = 0; k < BK; ++k) {
            float4 a0 = *(const float4*)&As[k][mA];
            float4 a1 = *(const float4*)&As[k][mA + 64];
            float4 b0 = *(const float4*)&Bs[k][nA];
            float4 b1 = *(const float4*)&Bs[k][nA + 64];
            float a[8] = {a0.x, a0.y, a0.z, a0.w, a1.x, a1.y, a1.z, a1.w};
            float b[8] = {b0.x, b0.y, b0.z, b0.w, b1.x, b1.y, b1.z, b1.w};
#pragma unroll
            for (int i = 0; i < 8; ++i)
#pragma unroll
                for (int j = 0; j < 8; ++j)
                    acc[i][j] = fmaf(a[i], b[j], acc[i][j]);
        }
    }

    float bb[8];
#pragma unroll
    for (int j = 0; j < 4; ++j) {
        bb[j]     = bias[(size_t)(n0 + nA + j)      * biasStride];
        bb[4 + j] = bias[(size_t)(n0 + nA + 64 + j) * biasStride];
    }
#pragma unroll
    for (int i = 0; i < 8; ++i) {
        int m = m0 + ((i < 4) ? (mA + i) : (64 + mA + (i - 4)));
        float* crow = C + (size_t)m * N + n0;
        float4 o0 = make_float4(acc[i][0] + bb[0], acc[i][1] + bb[1],
                                acc[i][2] + bb[2], acc[i][3] + bb[3]);
        float4 o1 = make_float4(acc[i][4] + bb[4], acc[i][5] + bb[5],
                                acc[i][6] + bb[6], acc[i][7] + bb[7]);
        *(float4*)(crow + nA)      = o0;
        *(float4*)(crow + nA + 64) = o1;
    }
}

// ---------------------------------------------------------------------------
// align[s,h] = sum_d Kc[s,d] * Q[s, 32d+h] / 64 ; masked fill 1e-20 (NOT -inf);
// softmax over h (32 lanes = 1 warp per row).
// ---------------------------------------------------------------------------
__global__ void attn_weights_kernel(const float* __restrict__ Q,
                                    const float* __restrict__ Kc,
                                    const int* __restrict__ mask,
                                    float* __restrict__ Wt)
{
    const int warp = threadIdx.x >> 5;
    const int h    = threadIdx.x & 31;
    const int s    = blockIdx.x * (blockDim.x >> 5) + warp;

    const float* q  = Q  + (size_t)s * E_DIM;
    const float* kc = Kc + (size_t)s * D_DIM;

    float acc = 0.f;
#pragma unroll 8
    for (int d = 0; d < D_DIM; ++d)
        acc = fmaf(kc[d], q[d * H_DIM + h], acc);

    acc *= (1.0f / 64.0f);                       // SCALE = sqrt(4096)
    if (mask[(size_t)s * H_DIM + h] == 0) acc = 1e-20f;

    // softmax over the 32-lane head axis (masked entries participate!)
    float mx = acc;
#pragma unroll
    for (int o = 16; o > 0; o >>= 1) mx = fmaxf(mx, __shfl_xor_sync(0xffffffffu, mx, o));
    float e = __expf(acc - mx);
    float sum = e;
#pragma unroll
    for (int o = 16; o > 0; o >>= 1) sum += __shfl_xor_sync(0xffffffffu, sum, o);

    Wt[(size_t)s * H_DIM + h] = e / sum;
}

// ---------------------------------------------------------------------------
// out[s,e] = V[s,e] * w[s, e%32]  (V was written in-place into d_out)
// ---------------------------------------------------------------------------
__global__ void scale_v_kernel(float* __restrict__ out, const float* __restrict__ Wt)
{
    size_t idx = ((size_t)blockIdx.x * blockDim.x + threadIdx.x) * 4;
    float4 v = *(float4*)(out + idx);
    const int s = (int)(idx >> 12);          // / 4096
    const int h = (int)(idx & 31);           // e % 32 (idx%4==0 -> h..h+3 <= 31)
    const float* w = Wt + (size_t)s * H_DIM;
    v.x *= w[h]; v.y *= w[h + 1]; v.z *= w[h + 2]; v.w *= w[h + 3];
    *(float4*)(out + idx) = v;
}

// ---------------------------------------------------------------------------
// Launch
// ---------------------------------------------------------------------------
extern "C" void kernel_launch(void* const* d_in, const int* in_sizes, int n_in,
                              void* d_out, int out_size)
{
    (void)in_sizes; (void)n_in; (void)out_size;

    const float* x    = (const float*)d_in[0];
    const float* Wq   = (const float*)d_in[1];
    const float* bq   = (const float*)d_in[2];
    const float* Wk   = (const float*)d_in[3];
    const float* bk   = (const float*)d_in[4];
    const float* Wv   = (const float*)d_in[5];
    const float* bv   = (const float*)d_in[6];
    const int*   mask = (const int*)d_in[7];
    float* out = (float*)d_out;

    float *Qp, *Kcp, *Wtp;
    cudaGetSymbolAddress((void**)&Qp,  g_Q);
    cudaGetSymbolAddress((void**)&Kcp, g_Kc);
    cudaGetSymbolAddress((void**)&Wtp, g_Wt);

    dim3 blk(256);
    // Q = x @ Wq.T + bq
    sgemm_tn_bias<<<dim3(E_DIM / BN, S_DIM / BM), blk>>>(x, Wq, bq, Qp,  E_DIM, E_DIM, E_DIM, 1);
    // Kc = x @ Wk[every 32nd row].T + bk[every 32nd]
    sgemm_tn_bias<<<dim3(D_DIM / BN, S_DIM / BM), blk>>>(x, Wk, bk, Kcp, D_DIM, E_DIM, E_DIM * H_DIM, H_DIM);
    // V = x @ Wv.T + bv  -> directly into d_out
    sgemm_tn_bias<<<dim3(E_DIM / BN, S_DIM / BM), blk>>>(x, Wv, bv, out, E_DIM, E_DIM, E_DIM, 1);
    // softmax weights
    attn_weights_kernel<<<S_DIM / 4, 128>>>(Qp, Kcp, mask, Wtp);
    // out *= weights
    scale_v_kernel<<<((size_t)S_DIM * E_DIM / 4) / 256, 256>>>(out, Wtp);
}

// round 3
// speedup vs baseline: 3.1666x; 3.1666x over previous
#include <cuda_runtime.h>
#include <cuda_bf16.h>
#include <cstdint>
#include <cstddef>

#define S_DIM 8192
#define E_DIM 4096
#define H_DIM 32
#define D_DIM 128

// ---------------------------------------------------------------------------
// Scratch (static __device__; no allocation allowed)
// ---------------------------------------------------------------------------
__device__ __nv_bfloat16 g_x_hi [(size_t)S_DIM * E_DIM];
__device__ __nv_bfloat16 g_x_lo [(size_t)S_DIM * E_DIM];
__device__ __nv_bfloat16 g_wq_hi[(size_t)E_DIM * E_DIM];
__device__ __nv_bfloat16 g_wq_lo[(size_t)E_DIM * E_DIM];
__device__ __nv_bfloat16 g_wv_hi[(size_t)E_DIM * E_DIM];
__device__ __nv_bfloat16 g_wv_lo[(size_t)E_DIM * E_DIM];
__device__ __nv_bfloat16 g_wk_hi[(size_t)D_DIM * E_DIM];
__device__ __nv_bfloat16 g_wk_lo[(size_t)D_DIM * E_DIM];
__device__ float g_bkc[D_DIM];
__device__ float g_Q [(size_t)S_DIM * E_DIM];
__device__ float g_Kc[(size_t)S_DIM * D_DIM];
__device__ float g_Wt[(size_t)S_DIM * H_DIM];

// ---------------------------------------------------------------------------
// PTX helpers (sm_80-era: legal under plain sm_103 target)
// ---------------------------------------------------------------------------
__device__ __forceinline__ uint32_t smem_u32(const void* p) {
    uint32_t a;
    asm("{ .reg .u64 t; cvta.to.shared.u64 t, %1; cvt.u32.u64 %0, t; }" : "=r"(a) : "l"(p));
    return a;
}
__device__ __forceinline__ void cp16(uint32_t s, const void* g) {
    asm volatile("cp.async.cg.shared.global [%0], [%1], 16;" :: "r"(s), "l"(g));
}
#define CP_COMMIT() asm volatile("cp.async.commit_group;" ::: "memory")
#define CP_WAIT(n)  asm volatile("cp.async.wait_group %0;" :: "n"(n) : "memory")

__device__ __forceinline__ void ldsm4(uint32_t& r0, uint32_t& r1, uint32_t& r2, uint32_t& r3,
                                      uint32_t a) {
    asm volatile("ldmatrix.sync.aligned.m8n8.x4.shared.b16 {%0,%1,%2,%3}, [%4];"
                 : "=r"(r0), "=r"(r1), "=r"(r2), "=r"(r3) : "r"(a));
}
__device__ __forceinline__ void mma16816(float* c, const uint32_t* a, const uint32_t* b) {
    asm volatile("mma.sync.aligned.m16n8k16.row.col.f32.bf16.bf16.f32 "
                 "{%0,%1,%2,%3}, {%4,%5,%6,%7}, {%8,%9}, {%0,%1,%2,%3};"
                 : "+f"(c[0]), "+f"(c[1]), "+f"(c[2]), "+f"(c[3])
                 : "r"(a[0]), "r"(a[1]), "r"(a[2]), "r"(a[3]), "r"(b[0]), "r"(b[1]));
}

// ---------------------------------------------------------------------------
// fp32 -> bf16 hi/lo split (vectorized x4)
// ---------------------------------------------------------------------------
__global__ void split_kernel(const float4* __restrict__ in,
                             __nv_bfloat162* __restrict__ hi,
                             __nv_bfloat162* __restrict__ lo, int n4)
{
    int i = blockIdx.x * blockDim.x + threadIdx.x;
    if (i >= n4) return;
    float4 v = in[i];
    __nv_bfloat16 hx = __float2bfloat16(v.x), hy = __float2bfloat16(v.y);
    __nv_bfloat16 hz = __float2bfloat16(v.z), hw = __float2bfloat16(v.w);
    hi[2 * i]     = __halves2bfloat162(hx, hy);
    hi[2 * i + 1] = __halves2bfloat162(hz, hw);
    lo[2 * i]     = __halves2bfloat162(__float2bfloat16(v.x - __bfloat162float(hx)),
                                       __float2bfloat16(v.y - __bfloat162float(hy)));
    lo[2 * i + 1] = __halves2bfloat162(__float2bfloat16(v.z - __bfloat162float(hz)),
                                       __float2bfloat16(v.w - __bfloat162float(hw)));
}

// Gather every 32nd row of Wk -> dense [128,4096] hi/lo, and bk -> bkc
__global__ void gather_wk_kernel(const float* __restrict__ Wk, const float* __restrict__ bk,
                                 __nv_bfloat16* __restrict__ hi, __nv_bfloat16* __restrict__ lo,
                                 float* __restrict__ bkc)
{
    int i = blockIdx.x * blockDim.x + threadIdx.x;   // over 131072 float4s
    int r = i >> 10;
    int c4 = i & 1023;
    float4 v = *(const float4*)(Wk + ((size_t)r * H_DIM) * E_DIM + c4 * 4);
    __nv_bfloat162* h2 = (__nv_bfloat162*)(hi + (size_t)r * E_DIM + c4 * 4);
    __nv_bfloat162* l2 = (__nv_bfloat162*)(lo + (size_t)r * E_DIM + c4 * 4);
    __nv_bfloat16 hx = __float2bfloat16(v.x), hy = __float2bfloat16(v.y);
    __nv_bfloat16 hz = __float2bfloat16(v.z), hw = __float2bfloat16(v.w);
    h2[0] = __halves2bfloat162(hx, hy);
    h2[1] = __halves2bfloat162(hz, hw);
    l2[0] = __halves2bfloat162(__float2bfloat16(v.x - __bfloat162float(hx)),
                               __float2bfloat16(v.y - __bfloat162float(hy)));
    l2[1] = __halves2bfloat162(__float2bfloat16(v.z - __bfloat162float(hz)),
                               __float2bfloat16(v.w - __bfloat162float(hw)));
    if (i < D_DIM) bkc[i] = bk[i * H_DIM];
}

// ---------------------------------------------------------------------------
// bf16x3 mma.sync GEMM:  C[M,N] = (Ahi+Alo)[M,K] @ (Bhi+Blo)[N,K]^T + bias
// CTA 128x128, K chunk 64 (bf16), 8 warps 4x2, warp tile 32x64, cp.async
// double buffer. Optional fused scale: C *= wt[m*32 + (n&31)].
// ---------------------------------------------------------------------------
#define KC 64
#define TILE_B 16384                 // 128 rows x 128 bytes
#define STAGE_B (4 * TILE_B)         // Ahi, Alo, Bhi, Blo
#define SMEM_TOTAL (2 * STAGE_B)     // 128 KB
#define N_CHUNKS (E_DIM / KC)        // 64

// stage tile loader: 128 rows x 128 bytes, SW128 xor swizzle
__device__ __forceinline__ void load_tile_cp(const char* __restrict__ g, uint32_t sdst, int tid)
{
#pragma unroll
    for (int j = 0; j < 4; ++j) {
        int i = tid + (j << 8);
        int r = i >> 3, seg = i & 7;
        uint32_t off = (uint32_t)((r << 7) + (((seg ^ (r & 7))) << 4));
        cp16(sdst + off, g + (size_t)r * (E_DIM * 2) + (seg << 4));
    }
}

__global__ __launch_bounds__(256, 1)
void gemm_mma_bf16x3(const __nv_bfloat16* __restrict__ Ahi, const __nv_bfloat16* __restrict__ Alo,
                     const __nv_bfloat16* __restrict__ Bhi, const __nv_bfloat16* __restrict__ Blo,
                     const float* __restrict__ bias, float* __restrict__ C,
                     int ldC, const float* __restrict__ fuseWt)
{
    extern __shared__ __align__(1024) char smem[];
    const int tid  = threadIdx.x;
    const int wid  = tid >> 5;
    const int lane = tid & 31;
    const int wm   = wid >> 1;          // 0..3
    const int wn   = wid & 1;           // 0..1
    const int m0 = blockIdx.y * 128;
    const int n0 = blockIdx.x * 128;

    const uint32_t sb = smem_u32(smem);

    const char* pAhi = (const char*)(Ahi + (size_t)m0 * E_DIM);
    const char* pAlo = (const char*)(Alo + (size_t)m0 * E_DIM);
    const char* pBhi = (const char*)(Bhi + (size_t)n0 * E_DIM);
    const char* pBlo = (const char*)(Blo + (size_t)n0 * E_DIM);

    float acc[2][8][4];
#pragma unroll
    for (int t = 0; t < 2; ++t)
#pragma unroll
        for (int j = 0; j < 8; ++j)
#pragma unroll
            for (int q = 0; q < 4; ++q) acc[t][j][q] = 0.f;

    // per-lane ldmatrix row bases (within 128-row tile)
    const int rowA0 = wm * 32 + (lane & 15);                       // t adds 16
    const int rowB0 = wn * 64 + ((lane >> 4) << 3) + (lane & 7);   // pair p adds 16
    const int segA  = (lane >> 4);            // 0/1, + ks*2
    const int segB  = ((lane >> 3) & 1);      // 0/1, + ks*2

    // prologue: chunk 0 -> stage 0
    {
        uint32_t su = sb;
        load_tile_cp(pAhi, su,              tid);
        load_tile_cp(pAlo, su + TILE_B,     tid);
        load_tile_cp(pBhi, su + 2 * TILE_B, tid);
        load_tile_cp(pBlo, su + 3 * TILE_B, tid);
        CP_COMMIT();
    }

    for (int c = 0; c < N_CHUNKS; ++c) {
        if (c + 1 < N_CHUNKS) {
            uint32_t su = sb + ((c + 1) & 1) * STAGE_B;
            size_t kb = (size_t)(c + 1) * (KC * 2);
            load_tile_cp(pAhi + kb, su,              tid);
            load_tile_cp(pAlo + kb, su + TILE_B,     tid);
            load_tile_cp(pBhi + kb, su + 2 * TILE_B, tid);
            load_tile_cp(pBlo + kb, su + 3 * TILE_B, tid);
            CP_COMMIT();
            CP_WAIT(1);
        } else {
            CP_WAIT(0);
        }
        __syncthreads();

        const uint32_t su = sb + (c & 1) * STAGE_B;
#pragma unroll
        for (int ks = 0; ks < 4; ++ks) {
            uint32_t ah[2][4], al[2][4];
#pragma unroll
            for (int t = 0; t < 2; ++t) {
                int row = rowA0 + t * 16;
                uint32_t off = (uint32_t)(row * 128 + (((ks * 2 + segA) ^ (row & 7)) << 4));
                ldsm4(ah[t][0], ah[t][1], ah[t][2], ah[t][3], su + off);
                ldsm4(al[t][0], al[t][1], al[t][2], al[t][3], su + TILE_B + off);
            }
            uint32_t bh[8][2], bl[8][2];
#pragma unroll
            for (int p = 0; p < 4; ++p) {
                int row = rowB0 + p * 16;
                uint32_t off = (uint32_t)(row * 128 + (((ks * 2 + segB) ^ (row & 7)) << 4));
                ldsm4(bh[2 * p][0], bh[2 * p][1], bh[2 * p + 1][0], bh[2 * p + 1][1],
                      su + 2 * TILE_B + off);
                ldsm4(bl[2 * p][0], bl[2 * p][1], bl[2 * p + 1][0], bl[2 * p + 1][1],
                      su + 3 * TILE_B + off);
            }
            // hi*hi
#pragma unroll
            for (int t = 0; t < 2; ++t)
#pragma unroll
                for (int j = 0; j < 8; ++j) mma16816(acc[t][j], ah[t], bh[j]);
            // hi*lo
#pragma unroll
            for (int t = 0; t < 2; ++t)
#pragma unroll
                for (int j = 0; j < 8; ++j) mma16816(acc[t][j], ah[t], bl[j]);
            // lo*hi
#pragma unroll
            for (int t = 0; t < 2; ++t)
#pragma unroll
                for (int j = 0; j < 8; ++j) mma16816(acc[t][j], al[t], bh[j]);
        }
        __syncthreads();
    }

    // epilogue
    const int rbase = m0 + wm * 32 + (lane >> 2);
    const int cbase = n0 + wn * 64 + (lane & 3) * 2;
#pragma unroll
    for (int t = 0; t < 2; ++t) {
        int row0 = rbase + t * 16;
#pragma unroll
        for (int j = 0; j < 8; ++j) {
            int col = cbase + j * 8;
            float b0 = bias[col], b1 = bias[col + 1];
            float2 v0 = make_float2(acc[t][j][0] + b0, acc[t][j][1] + b1);
            float2 v1 = make_float2(acc[t][j][2] + b0, acc[t][j][3] + b1);
            if (fuseWt) {
                int h = col & 31;
                const float* w0 = fuseWt + (size_t)row0 * H_DIM;
                const float* w1 = fuseWt + (size_t)(row0 + 8) * H_DIM;
                v0.x *= w0[h]; v0.y *= w0[h + 1];
                v1.x *= w1[h]; v1.y *= w1[h + 1];
            }
            *(float2*)(C + (size_t)row0 * ldC + col)       = v0;
            *(float2*)(C + (size_t)(row0 + 8) * ldC + col) = v1;
        }
    }
}

// ---------------------------------------------------------------------------
// align + softmax weights
// ---------------------------------------------------------------------------
__global__ void attn_weights_kernel(const float* __restrict__ Q,
                                    const float* __restrict__ Kc,
                                    const int* __restrict__ mask,
                                    float* __restrict__ Wt)
{
    const int warp = threadIdx.x >> 5;
    const int h = threadIdx.x & 31;
    const int s = blockIdx.x * (blockDim.x >> 5) + warp;

    const float* q = Q + (size_t)s * E_DIM;
    const float* kc = Kc + (size_t)s * D_DIM;

    float acc = 0.f;
#pragma unroll 8
    for (int d = 0; d < D_DIM; ++d)
        acc = fmaf(kc[d], q[d * H_DIM + h], acc);

    acc *= (1.0f / 64.0f);
    if (mask[(size_t)s * H_DIM + h] == 0) acc = 1e-20f;

    float mx = acc;
#pragma unroll
    for (int o = 16; o > 0; o >>= 1) mx = fmaxf(mx, __shfl_xor_sync(0xffffffffu, mx, o));
    float e = __expf(acc - mx);
    float sum = e;
#pragma unroll
    for (int o = 16; o > 0; o >>= 1) sum += __shfl_xor_sync(0xffffffffu, sum, o);

    Wt[(size_t)s * H_DIM + h] = e / sum;
}

// ---------------------------------------------------------------------------
// Launch
// ---------------------------------------------------------------------------
extern "C" void kernel_launch(void* const* d_in, const int* in_sizes, int n_in,
                              void* d_out, int out_size)
{
    (void)in_sizes; (void)n_in; (void)out_size;

    const float* x    = (const float*)d_in[0];
    const float* Wq   = (const float*)d_in[1];
    const float* bq   = (const float*)d_in[2];
    const float* Wk   = (const float*)d_in[3];
    const float* bk   = (const float*)d_in[4];
    const float* Wv   = (const float*)d_in[5];
    const float* bv   = (const float*)d_in[6];
    const int*   mask = (const int*)d_in[7];
    float* out = (float*)d_out;

    __nv_bfloat16 *xh, *xl, *qh, *ql, *vh, *vl, *kh, *kl;
    float *bkc, *Qp, *Kcp, *Wtp;
    cudaGetSymbolAddress((void**)&xh, g_x_hi);  cudaGetSymbolAddress((void**)&xl, g_x_lo);
    cudaGetSymbolAddress((void**)&qh, g_wq_hi); cudaGetSymbolAddress((void**)&ql, g_wq_lo);
    cudaGetSymbolAddress((void**)&vh, g_wv_hi); cudaGetSymbolAddress((void**)&vl, g_wv_lo);
    cudaGetSymbolAddress((void**)&kh, g_wk_hi); cudaGetSymbolAddress((void**)&kl, g_wk_lo);
    cudaGetSymbolAddress((void**)&bkc, g_bkc);
    cudaGetSymbolAddress((void**)&Qp, g_Q);
    cudaGetSymbolAddress((void**)&Kcp, g_Kc);
    cudaGetSymbolAddress((void**)&Wtp, g_Wt);

    cudaFuncSetAttribute(gemm_mma_bf16x3, cudaFuncAttributeMaxDynamicSharedMemorySize, SMEM_TOTAL);

    // conversions
    int n4x = (S_DIM * E_DIM) / 4;
    split_kernel<<<n4x / 256, 256>>>((const float4*)x, (__nv_bfloat162*)xh, (__nv_bfloat162*)xl, n4x);
    int n4w = (E_DIM * E_DIM) / 4;
    split_kernel<<<n4w / 256, 256>>>((const float4*)Wq, (__nv_bfloat162*)qh, (__nv_bfloat162*)ql, n4w);
    split_kernel<<<n4w / 256, 256>>>((const float4*)Wv, (__nv_bfloat162*)vh, (__nv_bfloat162*)vl, n4w);
    gather_wk_kernel<<<(D_DIM * E_DIM / 4) / 256, 256>>>(Wk, bk, kh, kl, bkc);

    // Q = x @ Wq.T + bq
    gemm_mma_bf16x3<<<dim3(E_DIM / 128, S_DIM / 128), 256, SMEM_TOTAL>>>(xh, xl, qh, ql, bq, Qp, E_DIM, nullptr);
    // Kc = x @ Wk_sub.T + bk_sub
    gemm_mma_bf16x3<<<dim3(1, S_DIM / 128), 256, SMEM_TOTAL>>>(xh, xl, kh, kl, bkc, Kcp, D_DIM, nullptr);
    // softmax weights
    attn_weights_kernel<<<S_DIM / 4, 128>>>(Qp, Kcp, mask, Wtp);
    // out = (x @ Wv.T + bv) * weights (fused epilogue)
    gemm_mma_bf16x3<<<dim3(E_DIM / 128, S_DIM / 128), 256, SMEM_TOTAL>>>(xh, xl, vh, vl, bv, out, E_DIM, Wtp);
}

// round 5
// speedup vs baseline: 4.3576x; 1.3761x over previous
#include <cuda_runtime.h>
#include <cuda_fp16.h>
#include <cstdint>
#include <cstddef>

#define S_DIM 8192
#define E_DIM 4096
#define H_DIM 32
#define D_DIM 128

// ---------------------------------------------------------------------------
// Scratch (static __device__; no allocation allowed)
// ---------------------------------------------------------------------------
__device__ __half g_x_hi[(size_t)S_DIM * E_DIM];
__device__ __half g_x_lo[(size_t)S_DIM * E_DIM];
__device__ __half g_wq  [(size_t)E_DIM * E_DIM];
__device__ __half g_wv  [(size_t)E_DIM * E_DIM];
__device__ __half g_wk  [(size_t)D_DIM * E_DIM];
__device__ float  g_bkc[D_DIM];
__device__ float  g_Q  [(size_t)S_DIM * E_DIM];
__device__ float  g_Kc [(size_t)S_DIM * D_DIM];
__device__ float  g_Wt [(size_t)S_DIM * H_DIM];

// ---------------------------------------------------------------------------
// PTX helpers (sm_80-era: legal under plain sm_103 target)
// ---------------------------------------------------------------------------
__device__ __forceinline__ uint32_t smem_u32(const void* p) {
    uint32_t a;
    asm("{ .reg .u64 t; cvta.to.shared.u64 t, %1; cvt.u32.u64 %0, t; }" : "=r"(a) : "l"(p));
    return a;
}
__device__ __forceinline__ void cp16(uint32_t s, const void* g) {
    asm volatile("cp.async.cg.shared.global [%0], [%1], 16;" :: "r"(s), "l"(g));
}
#define CP_COMMIT() asm volatile("cp.async.commit_group;" ::: "memory")
#define CP_WAIT(n)  asm volatile("cp.async.wait_group %0;" :: "n"(n) : "memory")

__device__ __forceinline__ void ldsm4(uint32_t& r0, uint32_t& r1, uint32_t& r2, uint32_t& r3,
                                      uint32_t a) {
    asm volatile("ldmatrix.sync.aligned.m8n8.x4.shared.b16 {%0,%1,%2,%3}, [%4];"
                 : "=r"(r0), "=r"(r1), "=r"(r2), "=r"(r3) : "r"(a));
}
__device__ __forceinline__ void mma16816(float* c, const uint32_t* a, const uint32_t* b) {
    asm volatile("mma.sync.aligned.m16n8k16.row.col.f32.f16.f16.f32 "
                 "{%0,%1,%2,%3}, {%4,%5,%6,%7}, {%8,%9}, {%0,%1,%2,%3};"
                 : "+f"(c[0]), "+f"(c[1]), "+f"(c[2]), "+f"(c[3])
                 : "r"(a[0]), "r"(a[1]), "r"(a[2]), "r"(a[3]), "r"(b[0]), "r"(b[1]));
}

// ---------------------------------------------------------------------------
// fp32 -> fp16 hi/lo split (x) ; fp32 -> fp16 (weights)
// ---------------------------------------------------------------------------
__global__ void split2_kernel(const float4* __restrict__ in,
                              __half2* __restrict__ hi,
                              __half2* __restrict__ lo, int n4)
{
    int i = blockIdx.x * blockDim.x + threadIdx.x;
    if (i >= n4) return;
    float4 v = in[i];
    __half hx = __float2half_rn(v.x), hy = __float2half_rn(v.y);
    __half hz = __float2half_rn(v.z), hw = __float2half_rn(v.w);
    hi[2 * i]     = __halves2half2(hx, hy);
    hi[2 * i + 1] = __halves2half2(hz, hw);
    lo[2 * i]     = __halves2half2(__float2half_rn(v.x - __half2float(hx)),
                                   __float2half_rn(v.y - __half2float(hy)));
    lo[2 * i + 1] = __halves2half2(__float2half_rn(v.z - __half2float(hz)),
                                   __float2half_rn(v.w - __half2float(hw)));
}

__global__ void cvt_kernel(const float4* __restrict__ in, __half2* __restrict__ out, int n4)
{
    int i = blockIdx.x * blockDim.x + threadIdx.x;
    if (i >= n4) return;
    float4 v = in[i];
    out[2 * i]     = __halves2half2(__float2half_rn(v.x), __float2half_rn(v.y));
    out[2 * i + 1] = __halves2half2(__float2half_rn(v.z), __float2half_rn(v.w));
}

// Gather every 32nd row of Wk -> dense fp16 [128,4096], and bk -> bkc
__global__ void gather_wk_kernel(const float* __restrict__ Wk, const float* __restrict__ bk,
                                 __half* __restrict__ o, float* __restrict__ bkc)
{
    int i = blockIdx.x * blockDim.x + threadIdx.x;   // over 131072 float4s
    int r = i >> 10;
    int c4 = i & 1023;
    float4 v = *(const float4*)(Wk + ((size_t)r * H_DIM) * E_DIM + c4 * 4);
    __half2* o2 = (__half2*)(o + (size_t)r * E_DIM + c4 * 4);
    o2[0] = __halves2half2(__float2half_rn(v.x), __float2half_rn(v.y));
    o2[1] = __halves2half2(__float2half_rn(v.z), __float2half_rn(v.w));
    if (i < D_DIM) bkc[i] = bk[i * H_DIM];
}

// ---------------------------------------------------------------------------
// fp16x2 mma.sync GEMM:  C[M,N] = (Ahi+Alo)[M,K] @ B[N,K]^T + bias
// CTA 128x128, K chunk 64, 8 warps 4x2 (warp tile 32x64),
// 3-stage cp.async pipeline. Optional fused scale: C *= wt[m*32 + (n&31)].
// ---------------------------------------------------------------------------
#define KC 64
#define TILE_B 16384                 // 128 rows x 128 bytes
#define STAGE_B (3 * TILE_B)         // Ahi, Alo, B
#define N_STAGES 3
#define SMEM_TOTAL (N_STAGES * STAGE_B)   // 144 KB
#define N_CHUNKS (E_DIM / KC)        // 64

// stage tile loader: 128 rows x 128 bytes, SW128 xor swizzle
__device__ __forceinline__ void load_tile_cp(const char* __restrict__ g, uint32_t sdst, int tid)
{
#pragma unroll
    for (int j = 0; j < 4; ++j) {
        int i = tid + (j << 8);
        int r = i >> 3, seg = i & 7;
        uint32_t off = (uint32_t)((r << 7) + (((seg ^ (r & 7))) << 4));
        cp16(sdst + off, g + (size_t)r * (E_DIM * 2) + (seg << 4));
    }
}

__device__ __forceinline__ void load_stage(const char* pAhi, const char* pAlo, const char* pB,
                                           uint32_t su, size_t kb, int tid)
{
    load_tile_cp(pAhi + kb, su,              tid);
    load_tile_cp(pAlo + kb, su + TILE_B,     tid);
    load_tile_cp(pB   + kb, su + 2 * TILE_B, tid);
    CP_COMMIT();
}

__global__ __launch_bounds__(256, 1)
void gemm_mma_fp16x2(const __half* __restrict__ Ahi, const __half* __restrict__ Alo,
                     const __half* __restrict__ B,
                     const float* __restrict__ bias, float* __restrict__ C,
                     int ldC, const float* __restrict__ fuseWt)
{
    extern __shared__ __align__(1024) char smem[];
    const int tid  = threadIdx.x;
    const int wid  = tid >> 5;
    const int lane = tid & 31;
    const int wm   = wid >> 1;          // 0..3
    const int wn   = wid & 1;           // 0..1
    const int m0 = blockIdx.y * 128;
    const int n0 = blockIdx.x * 128;

    const uint32_t sb = smem_u32(smem);

    const char* pAhi = (const char*)(Ahi + (size_t)m0 * E_DIM);
    const char* pAlo = (const char*)(Alo + (size_t)m0 * E_DIM);
    const char* pB   = (const char*)(B   + (size_t)n0 * E_DIM);

    float acc[2][8][4];
#pragma unroll
    for (int t = 0; t < 2; ++t)
#pragma unroll
        for (int j = 0; j < 8; ++j)
#pragma unroll
            for (int q = 0; q < 4; ++q) acc[t][j][q] = 0.f;

    const int rowA0 = wm * 32 + (lane & 15);                       // t adds 16
    const int rowB0 = wn * 64 + ((lane >> 4) << 3) + (lane & 7);   // pair p adds 16
    const int segA  = (lane >> 4);
    const int segB  = ((lane >> 3) & 1);

    // prologue: chunks 0,1 -> stages 0,1
    load_stage(pAhi, pAlo, pB, sb,           0,          tid);
    load_stage(pAhi, pAlo, pB, sb + STAGE_B, (size_t)KC * 2, tid);

    for (int c = 0; c < N_CHUNKS; ++c) {
        if (c == N_CHUNKS - 1) { CP_WAIT(0); } else { CP_WAIT(1); }
        __syncthreads();   // all warps finished chunk c-1's stage before overwrite
        if (c + 2 < N_CHUNKS) {
            uint32_t su = sb + ((c + 2) % N_STAGES) * STAGE_B;
            load_stage(pAhi, pAlo, pB, su, (size_t)(c + 2) * (KC * 2), tid);
        }

        const uint32_t su = sb + (c % N_STAGES) * STAGE_B;
#pragma unroll
        for (int ks = 0; ks < 4; ++ks) {
            uint32_t ah[2][4], al[2][4];
#pragma unroll
            for (int t = 0; t < 2; ++t) {
                int row = rowA0 + t * 16;
                uint32_t off = (uint32_t)(row * 128 + (((ks * 2 + segA) ^ (row & 7)) << 4));
                ldsm4(ah[t][0], ah[t][1], ah[t][2], ah[t][3], su + off);
                ldsm4(al[t][0], al[t][1], al[t][2], al[t][3], su + TILE_B + off);
            }
            uint32_t bh[8][2];
#pragma unroll
            for (int p = 0; p < 4; ++p) {
                int row = rowB0 + p * 16;
                uint32_t off = (uint32_t)(row * 128 + (((ks * 2 + segB) ^ (row & 7)) << 4));
                ldsm4(bh[2 * p][0], bh[2 * p][1], bh[2 * p + 1][0], bh[2 * p + 1][1],
                      su + 2 * TILE_B + off);
            }
            // hi pass
#pragma unroll
            for (int t = 0; t < 2; ++t)
#pragma unroll
                for (int j = 0; j < 8; ++j) mma16816(acc[t][j], ah[t], bh[j]);
            // lo pass
#pragma unroll
            for (int t = 0; t < 2; ++t)
#pragma unroll
                for (int j = 0; j < 8; ++j) mma16816(acc[t][j], al[t], bh[j]);
        }
        __syncthreads();
    }

    // epilogue
    const int rbase = m0 + wm * 32 + (lane >> 2);
    const int cbase = n0 + wn * 64 + (lane & 3) * 2;
#pragma unroll
    for (int t = 0; t < 2; ++t) {
        int row0 = rbase + t * 16;
#pragma unroll
        for (int j = 0; j < 8; ++j) {
            int col = cbase + j * 8;
            float b0 = bias[col], b1 = bias[col + 1];
            float2 v0 = make_float2(acc[t][j][0] + b0, acc[t][j][1] + b1);
            float2 v1 = make_float2(acc[t][j][2] + b0, acc[t][j][3] + b1);
            if (fuseWt) {
                int h = col & 31;
                const float* w0 = fuseWt + (size_t)row0 * H_DIM;
                const float* w1 = fuseWt + (size_t)(row0 + 8) * H_DIM;
                v0.x *= w0[h]; v0.y *= w0[h + 1];
                v1.x *= w1[h]; v1.y *= w1[h + 1];
            }
            *(float2*)(C + (size_t)row0 * ldC + col)       = v0;
            *(float2*)(C + (size_t)(row0 + 8) * ldC + col) = v1;
        }
    }
}

// ---------------------------------------------------------------------------
// align + softmax weights
// ---------------------------------------------------------------------------
__global__ void attn_weights_kernel(const float* __restrict__ Q,
                                    const float* __restrict__ Kc,
                                    const int* __restrict__ mask,
                                    float* __restrict__ Wt)
{
    const int warp = threadIdx.x >> 5;
    const int h = threadIdx.x & 31;
    const int s = blockIdx.x * (blockDim.x >> 5) + warp;

    const float* q = Q + (size_t)s * E_DIM;
    const float* kc = Kc + (size_t)s * D_DIM;

    float acc = 0.f;
#pragma unroll 8
    for (int d = 0; d < D_DIM; ++d)
        acc = fmaf(kc[d], q[d * H_DIM + h], acc);

    acc *= (1.0f / 64.0f);
    if (mask[(size_t)s * H_DIM + h] == 0) acc = 1e-20f;

    float mx = acc;
#pragma unroll
    for (int o = 16; o > 0; o >>= 1) mx = fmaxf(mx, __shfl_xor_sync(0xffffffffu, mx, o));
    float e = __expf(acc - mx);
    float sum = e;
#pragma unroll
    for (int o = 16; o > 0; o >>= 1) sum += __shfl_xor_sync(0xffffffffu, sum, o);

    Wt[(size_t)s * H_DIM + h] = e / sum;
}

// ---------------------------------------------------------------------------
// Launch
// ---------------------------------------------------------------------------
extern "C" void kernel_launch(void* const* d_in, const int* in_sizes, int n_in,
                              void* d_out, int out_size)
{
    (void)in_sizes; (void)n_in; (void)out_size;

    const float* x    = (const float*)d_in[0];
    const float* Wq   = (const float*)d_in[1];
    const float* bq   = (const float*)d_in[2];
    const float* Wk   = (const float*)d_in[3];
    const float* bk   = (const float*)d_in[4];
    const float* Wv   = (const float*)d_in[5];
    const float* bv   = (const float*)d_in[6];
    const int*   mask = (const int*)d_in[7];
    float* out = (float*)d_out;

    __half *xh, *xl, *wq, *wv, *wk;
    float *bkc, *Qp, *Kcp, *Wtp;
    cudaGetSymbolAddress((void**)&xh, g_x_hi);
    cudaGetSymbolAddress((void**)&xl, g_x_lo);
    cudaGetSymbolAddress((void**)&wq, g_wq);
    cudaGetSymbolAddress((void**)&wv, g_wv);
    cudaGetSymbolAddress((void**)&wk, g_wk);
    cudaGetSymbolAddress((void**)&bkc, g_bkc);
    cudaGetSymbolAddress((void**)&Qp, g_Q);
    cudaGetSymbolAddress((void**)&Kcp, g_Kc);
    cudaGetSymbolAddress((void**)&Wtp, g_Wt);

    cudaFuncSetAttribute(gemm_mma_fp16x2, cudaFuncAttributeMaxDynamicSharedMemorySize, SMEM_TOTAL);

    // conversions
    int n4x = (S_DIM * E_DIM) / 4;
    split2_kernel<<<n4x / 256, 256>>>((const float4*)x, (__half2*)xh, (__half2*)xl, n4x);
    int n4w = (E_DIM * E_DIM) / 4;
    cvt_kernel<<<n4w / 256, 256>>>((const float4*)Wq, (__half2*)wq, n4w);
    cvt_kernel<<<n4w / 256, 256>>>((const float4*)Wv, (__half2*)wv, n4w);
    gather_wk_kernel<<<(D_DIM * E_DIM / 4) / 256, 256>>>(Wk, bk, wk, bkc);

    // Q = x @ Wq.T + bq
    gemm_mma_fp16x2<<<dim3(E_DIM / 128, S_DIM / 128), 256, SMEM_TOTAL>>>(xh, xl, wq, bq, Qp, E_DIM, nullptr);
    // Kc = x @ Wk_sub.T + bk_sub
    gemm_mma_fp16x2<<<dim3(1, S_DIM / 128), 256, SMEM_TOTAL>>>(xh, xl, wk, bkc, Kcp, D_DIM, nullptr);
    // softmax weights
    attn_weights_kernel<<<S_DIM / 4, 128>>>(Qp, Kcp, mask, Wtp);
    // out = (x @ Wv.T + bv) * weights (fused epilogue)
    gemm_mma_fp16x2<<<dim3(E_DIM / 128, S_DIM / 128), 256, SMEM_TOTAL>>>(xh, xl, wv, bv, out, E_DIM, Wtp);
}

// round 6
// speedup vs baseline: 7.3679x; 1.6908x over previous
#include <cuda_runtime.h>
#include <cuda_fp16.h>
#include <cstdint>
#include <cstddef>

#define S_DIM 8192
#define E_DIM 4096
#define H_DIM 32
#define D_DIM 128

// ---------------------------------------------------------------------------
// Scratch (static __device__; no allocation allowed)
// ---------------------------------------------------------------------------
__device__ __half g_x [(size_t)S_DIM * E_DIM];
__device__ __half g_wq[(size_t)E_DIM * E_DIM];
__device__ __half g_wv[(size_t)E_DIM * E_DIM];
__device__ __half g_wk[(size_t)D_DIM * E_DIM];
__device__ float  g_bkc[D_DIM];
__device__ float  g_Q  [(size_t)S_DIM * E_DIM];
__device__ float  g_Kc [(size_t)S_DIM * D_DIM];
__device__ float  g_Wt [(size_t)S_DIM * H_DIM];

// ---------------------------------------------------------------------------
// PTX helpers (sm_80-era: legal under plain sm_103 target)
// ---------------------------------------------------------------------------
__device__ __forceinline__ uint32_t smem_u32(const void* p) {
    uint32_t a;
    asm("{ .reg .u64 t; cvta.to.shared.u64 t, %1; cvt.u32.u64 %0, t; }" : "=r"(a) : "l"(p));
    return a;
}
__device__ __forceinline__ void cp16(uint32_t s, const void* g) {
    asm volatile("cp.async.cg.shared.global [%0], [%1], 16;" :: "r"(s), "l"(g));
}
#define CP_COMMIT() asm volatile("cp.async.commit_group;" ::: "memory")
#define CP_WAIT(n)  asm volatile("cp.async.wait_group %0;" :: "n"(n) : "memory")

__device__ __forceinline__ void ldsm4(uint32_t& r0, uint32_t& r1, uint32_t& r2, uint32_t& r3,
                                      uint32_t a) {
    asm volatile("ldmatrix.sync.aligned.m8n8.x4.shared.b16 {%0,%1,%2,%3}, [%4];"
                 : "=r"(r0), "=r"(r1), "=r"(r2), "=r"(r3) : "r"(a));
}
__device__ __forceinline__ void mma16816(float* c, const uint32_t* a, const uint32_t* b) {
    asm volatile("mma.sync.aligned.m16n8k16.row.col.f32.f16.f16.f32 "
                 "{%0,%1,%2,%3}, {%4,%5,%6,%7}, {%8,%9}, {%0,%1,%2,%3};"
                 : "+f"(c[0]), "+f"(c[1]), "+f"(c[2]), "+f"(c[3])
                 : "r"(a[0]), "r"(a[1]), "r"(a[2]), "r"(a[3]), "r"(b[0]), "r"(b[1]));
}

// ---------------------------------------------------------------------------
// fp32 -> fp16 conversion (vectorized x4)
// ---------------------------------------------------------------------------
__global__ void cvt_kernel(const float4* __restrict__ in, __half2* __restrict__ out, int n4)
{
    int i = blockIdx.x * blockDim.x + threadIdx.x;
    if (i >= n4) return;
    float4 v = in[i];
    out[2 * i]     = __halves2half2(__float2half_rn(v.x), __float2half_rn(v.y));
    out[2 * i + 1] = __halves2half2(__float2half_rn(v.z), __float2half_rn(v.w));
}

// Gather every 32nd row of Wk -> dense fp16 [128,4096], and bk -> bkc
__global__ void gather_wk_kernel(const float* __restrict__ Wk, const float* __restrict__ bk,
                                 __half* __restrict__ o, float* __restrict__ bkc)
{
    int i = blockIdx.x * blockDim.x + threadIdx.x;   // over 131072 float4s
    int r = i >> 10;
    int c4 = i & 1023;
    float4 v = *(const float4*)(Wk + ((size_t)r * H_DIM) * E_DIM + c4 * 4);
    __half2* o2 = (__half2*)(o + (size_t)r * E_DIM + c4 * 4);
    o2[0] = __halves2half2(__float2half_rn(v.x), __float2half_rn(v.y));
    o2[1] = __halves2half2(__float2half_rn(v.z), __float2half_rn(v.w));
    if (i < D_DIM) bkc[i] = bk[i * H_DIM];
}

// ---------------------------------------------------------------------------
// fp16 mma.sync GEMM:  C[M,N] = A[M,K] @ B[N,K]^T + bias
// CTA 128x128, K chunk 64, 8 warps 4x2 (warp tile 32x64),
// 4-stage cp.async pipeline (prefetch distance 3).
// Optional fused scale: C *= wt[m*32 + (n&31)].
// ---------------------------------------------------------------------------
#define KC 64
#define TILE_B 16384                      // 128 rows x 128 bytes
#define STAGE_B (2 * TILE_B)              // A, B
#define N_STAGES 4
#define SMEM_TOTAL (N_STAGES * STAGE_B)   // 128 KB
#define N_CHUNKS (E_DIM / KC)             // 64

// stage tile loader: 128 rows x 128 bytes, SW128 xor swizzle
__device__ __forceinline__ void load_tile_cp(const char* __restrict__ g, uint32_t sdst, int tid)
{
#pragma unroll
    for (int j = 0; j < 4; ++j) {
        int i = tid + (j << 8);
        int r = i >> 3, seg = i & 7;
        uint32_t off = (uint32_t)((r << 7) + (((seg ^ (r & 7))) << 4));
        cp16(sdst + off, g + (size_t)r * (E_DIM * 2) + (seg << 4));
    }
}

__device__ __forceinline__ void load_stage(const char* pA, const char* pB,
                                           uint32_t su, size_t kb, int tid)
{
    load_tile_cp(pA + kb, su,          tid);
    load_tile_cp(pB + kb, su + TILE_B, tid);
    CP_COMMIT();
}

__global__ __launch_bounds__(256, 1)
void gemm_mma_fp16(const __half* __restrict__ A, const __half* __restrict__ B,
                   const float* __restrict__ bias, float* __restrict__ C,
                   int ldC, const float* __restrict__ fuseWt)
{
    extern __shared__ __align__(1024) char smem[];
    const int tid  = threadIdx.x;
    const int wid  = tid >> 5;
    const int lane = tid & 31;
    const int wm   = wid >> 1;          // 0..3
    const int wn   = wid & 1;           // 0..1
    const int m0 = blockIdx.y * 128;
    const int n0 = blockIdx.x * 128;

    const uint32_t sb = smem_u32(smem);

    const char* pA = (const char*)(A + (size_t)m0 * E_DIM);
    const char* pB = (const char*)(B + (size_t)n0 * E_DIM);

    float acc[2][8][4];
#pragma unroll
    for (int t = 0; t < 2; ++t)
#pragma unroll
        for (int j = 0; j < 8; ++j)
#pragma unroll
            for (int q = 0; q < 4; ++q) acc[t][j][q] = 0.f;

    const int rowA0 = wm * 32 + (lane & 15);                       // t adds 16
    const int rowB0 = wn * 64 + ((lane >> 4) << 3) + (lane & 7);   // pair p adds 16
    const int segA  = (lane >> 4);
    const int segB  = ((lane >> 3) & 1);

    // prologue: chunks 0,1,2 -> stages 0,1,2
    load_stage(pA, pB, sb,               0,                 tid);
    load_stage(pA, pB, sb + STAGE_B,     (size_t)KC * 2,     tid);
    load_stage(pA, pB, sb + 2 * STAGE_B, (size_t)KC * 2 * 2, tid);

    for (int c = 0; c < N_CHUNKS; ++c) {
        // wait until chunk c's group is complete
        if (c < N_CHUNKS - 2)      { CP_WAIT(2); }
        else if (c == N_CHUNKS - 2){ CP_WAIT(1); }
        else                       { CP_WAIT(0); }
        __syncthreads();   // all warps done with the stage we're about to overwrite
        if (c + 3 < N_CHUNKS) {
            uint32_t su = sb + ((c + 3) & 3) * STAGE_B;
            load_stage(pA, pB, su, (size_t)(c + 3) * (KC * 2), tid);
        }

        const uint32_t su = sb + (c & 3) * STAGE_B;
#pragma unroll
        for (int ks = 0; ks < 4; ++ks) {
            uint32_t ah[2][4];
#pragma unroll
            for (int t = 0; t < 2; ++t) {
                int row = rowA0 + t * 16;
                uint32_t off = (uint32_t)(row * 128 + (((ks * 2 + segA) ^ (row & 7)) << 4));
                ldsm4(ah[t][0], ah[t][1], ah[t][2], ah[t][3], su + off);
            }
            uint32_t bh[8][2];
#pragma unroll
            for (int p = 0; p < 4; ++p) {
                int row = rowB0 + p * 16;
                uint32_t off = (uint32_t)(row * 128 + (((ks * 2 + segB) ^ (row & 7)) << 4));
                ldsm4(bh[2 * p][0], bh[2 * p][1], bh[2 * p + 1][0], bh[2 * p + 1][1],
                      su + TILE_B + off);
            }
#pragma unroll
            for (int t = 0; t < 2; ++t)
#pragma unroll
                for (int j = 0; j < 8; ++j) mma16816(acc[t][j], ah[t], bh[j]);
        }
    }

    // epilogue
    const int rbase = m0 + wm * 32 + (lane >> 2);
    const int cbase = n0 + wn * 64 + (lane & 3) * 2;
#pragma unroll
    for (int t = 0; t < 2; ++t) {
        int row0 = rbase + t * 16;
#pragma unroll
        for (int j = 0; j < 8; ++j) {
            int col = cbase + j * 8;
            float b0 = bias[col], b1 = bias[col + 1];
            float2 v0 = make_float2(acc[t][j][0] + b0, acc[t][j][1] + b1);
            float2 v1 = make_float2(acc[t][j][2] + b0, acc[t][j][3] + b1);
            if (fuseWt) {
                int h = col & 31;
                const float* w0 = fuseWt + (size_t)row0 * H_DIM;
                const float* w1 = fuseWt + (size_t)(row0 + 8) * H_DIM;
                v0.x *= w0[h]; v0.y *= w0[h + 1];
                v1.x *= w1[h]; v1.y *= w1[h + 1];
            }
            *(float2*)(C + (size_t)row0 * ldC + col)       = v0;
            *(float2*)(C + (size_t)(row0 + 8) * ldC + col) = v1;
        }
    }
}

// ---------------------------------------------------------------------------
// align + softmax weights
// ---------------------------------------------------------------------------
__global__ void attn_weights_kernel(const float* __restrict__ Q,
                                    const float* __restrict__ Kc,
                                    const int* __restrict__ mask,
                                    float* __restrict__ Wt)
{
    const int warp = threadIdx.x >> 5;
    const int h = threadIdx.x & 31;
    const int s = blockIdx.x * (blockDim.x >> 5) + warp;

    const float* q = Q + (size_t)s * E_DIM;
    const float* kc = Kc + (size_t)s * D_DIM;

    float acc = 0.f;
#pragma unroll 8
    for (int d = 0; d < D_DIM; ++d)
        acc = fmaf(kc[d], q[d * H_DIM + h], acc);

    acc *= (1.0f / 64.0f);
    if (mask[(size_t)s * H_DIM + h] == 0) acc = 1e-20f;

    float mx = acc;
#pragma unroll
    for (int o = 16; o > 0; o >>= 1) mx = fmaxf(mx, __shfl_xor_sync(0xffffffffu, mx, o));
    float e = __expf(acc - mx);
    float sum = e;
#pragma unroll
    for (int o = 16; o > 0; o >>= 1) sum += __shfl_xor_sync(0xffffffffu, sum, o);

    Wt[(size_t)s * H_DIM + h] = e / sum;
}

// ---------------------------------------------------------------------------
// Launch
// ---------------------------------------------------------------------------
extern "C" void kernel_launch(void* const* d_in, const int* in_sizes, int n_in,
                              void* d_out, int out_size)
{
    (void)in_sizes; (void)n_in; (void)out_size;

    const float* x    = (const float*)d_in[0];
    const float* Wq   = (const float*)d_in[1];
    const float* bq   = (const float*)d_in[2];
    const float* Wk   = (const float*)d_in[3];
    const float* bk   = (const float*)d_in[4];
    const float* Wv   = (const float*)d_in[5];
    const float* bv   = (const float*)d_in[6];
    const int*   mask = (const int*)d_in[7];
    float* out = (float*)d_out;

    __half *xh, *wq, *wv, *wk;
    float *bkc, *Qp, *Kcp, *Wtp;
    cudaGetSymbolAddress((void**)&xh, g_x);
    cudaGetSymbolAddress((void**)&wq, g_wq);
    cudaGetSymbolAddress((void**)&wv, g_wv);
    cudaGetSymbolAddress((void**)&wk, g_wk);
    cudaGetSymbolAddress((void**)&bkc, g_bkc);
    cudaGetSymbolAddress((void**)&Qp, g_Q);
    cudaGetSymbolAddress((void**)&Kcp, g_Kc);
    cudaGetSymbolAddress((void**)&Wtp, g_Wt);

    cudaFuncSetAttribute(gemm_mma_fp16, cudaFuncAttributeMaxDynamicSharedMemorySize, SMEM_TOTAL);

    // conversions
    int n4x = (S_DIM * E_DIM) / 4;
    cvt_kernel<<<n4x / 256, 256>>>((const float4*)x, (__half2*)xh, n4x);
    int n4w = (E_DIM * E_DIM) / 4;
    cvt_kernel<<<n4w / 256, 256>>>((const float4*)Wq, (__half2*)wq, n4w);
    cvt_kernel<<<n4w / 256, 256>>>((const float4*)Wv, (__half2*)wv, n4w);
    gather_wk_kernel<<<(D_DIM * E_DIM / 4) / 256, 256>>>(Wk, bk, wk, bkc);

    // Q = x @ Wq.T + bq
    gemm_mma_fp16<<<dim3(E_DIM / 128, S_DIM / 128), 256, SMEM_TOTAL>>>(xh, wq, bq, Qp, E_DIM, nullptr);
    // Kc = x @ Wk_sub.T + bk_sub
    gemm_mma_fp16<<<dim3(1, S_DIM / 128), 256, SMEM_TOTAL>>>(xh, wk, bkc, Kcp, D_DIM, nullptr);
    // softmax weights
    attn_weights_kernel<<<S_DIM / 4, 128>>>(Qp, Kcp, mask, Wtp);
    // out = (x @ Wv.T + bv) * weights (fused epilogue)
    gemm_mma_fp16<<<dim3(E_DIM / 128, S_DIM / 128), 256, SMEM_TOTAL>>>(xh, wv, bv, out, E_DIM, Wtp);
}

// round 7
// speedup vs baseline: 8.9405x; 1.2134x over previous
#include <cuda_runtime.h>
#include <cuda_fp16.h>
#include <cstdint>
#include <cstddef>

#define S_DIM 8192
#define E_DIM 4096
#define H_DIM 32
#define D_DIM 128

// ---------------------------------------------------------------------------
// Scratch (static __device__; no allocation allowed)
// ---------------------------------------------------------------------------
__device__ __half g_x [(size_t)S_DIM * E_DIM];
__device__ __half g_wq[(size_t)E_DIM * E_DIM];
__device__ __half g_wv[(size_t)E_DIM * E_DIM];
__device__ __half g_wk[(size_t)D_DIM * E_DIM];
__device__ float  g_bkc[D_DIM];
__device__ float  g_Q  [(size_t)S_DIM * E_DIM];
__device__ float  g_Kc [(size_t)S_DIM * D_DIM];
__device__ float  g_Wt [(size_t)S_DIM * H_DIM];

// ---------------------------------------------------------------------------
// PTX helpers (sm_80-era: legal under plain sm_103 target)
// ---------------------------------------------------------------------------
__device__ __forceinline__ uint32_t smem_u32(const void* p) {
    uint32_t a;
    asm("{ .reg .u64 t; cvta.to.shared.u64 t, %1; cvt.u32.u64 %0, t; }" : "=r"(a) : "l"(p));
    return a;
}
__device__ __forceinline__ void cp16(uint32_t s, const void* g) {
    asm volatile("cp.async.cg.shared.global [%0], [%1], 16;" :: "r"(s), "l"(g));
}
#define CP_COMMIT() asm volatile("cp.async.commit_group;" ::: "memory")
#define CP_WAIT(n)  asm volatile("cp.async.wait_group %0;" :: "n"(n) : "memory")

__device__ __forceinline__ void ldsm4(uint32_t& r0, uint32_t& r1, uint32_t& r2, uint32_t& r3,
                                      uint32_t a) {
    asm volatile("ldmatrix.sync.aligned.m8n8.x4.shared.b16 {%0,%1,%2,%3}, [%4];"
                 : "=r"(r0), "=r"(r1), "=r"(r2), "=r"(r3) : "r"(a));
}
__device__ __forceinline__ void mma16816(float* c, const uint32_t* a, const uint32_t* b) {
    asm volatile("mma.sync.aligned.m16n8k16.row.col.f32.f16.f16.f32 "
                 "{%0,%1,%2,%3}, {%4,%5,%6,%7}, {%8,%9}, {%0,%1,%2,%3};"
                 : "+f"(c[0]), "+f"(c[1]), "+f"(c[2]), "+f"(c[3])
                 : "r"(a[0]), "r"(a[1]), "r"(a[2]), "r"(a[3]), "r"(b[0]), "r"(b[1]));
}

// ---------------------------------------------------------------------------
// fp32 -> fp16 conversion (vectorized x4)
// ---------------------------------------------------------------------------
__global__ void cvt_kernel(const float4* __restrict__ in, __half2* __restrict__ out, int n4)
{
    int i = blockIdx.x * blockDim.x + threadIdx.x;
    if (i >= n4) return;
    float4 v = in[i];
    out[2 * i]     = __halves2half2(__float2half_rn(v.x), __float2half_rn(v.y));
    out[2 * i + 1] = __halves2half2(__float2half_rn(v.z), __float2half_rn(v.w));
}

// Gather every 32nd row of Wk -> dense fp16 [128,4096], and bk -> bkc
__global__ void gather_wk_kernel(const float* __restrict__ Wk, const float* __restrict__ bk,
                                 __half* __restrict__ o, float* __restrict__ bkc)
{
    int i = blockIdx.x * blockDim.x + threadIdx.x;   // over 131072 float4s
    int r = i >> 10;
    int c4 = i & 1023;
    float4 v = *(const float4*)(Wk + ((size_t)r * H_DIM) * E_DIM + c4 * 4);
    __half2* o2 = (__half2*)(o + (size_t)r * E_DIM + c4 * 4);
    o2[0] = __halves2half2(__float2half_rn(v.x), __float2half_rn(v.y));
    o2[1] = __halves2half2(__float2half_rn(v.z), __float2half_rn(v.w));
    if (i < D_DIM) bkc[i] = bk[i * H_DIM];
}

// ---------------------------------------------------------------------------
// fp16 mma.sync GEMM:  C[M,N] = A[M,K] @ B[N,K]^T + bias
// CTA 128x128, 4 warps in 2x2 (warp tile 64x64), K chunk 64,
// 3-stage cp.async pipeline, 2 CTAs/SM.
// Optional fused scale: C *= wt[m*32 + (n&31)].
// ---------------------------------------------------------------------------
#define KC 64
#define TILE_B 16384                      // 128 rows x 128 bytes
#define STAGE_B (2 * TILE_B)              // A, B
#define N_STAGES 3
#define SMEM_TOTAL (N_STAGES * STAGE_B)   // 96 KB
#define N_CHUNKS (E_DIM / KC)             // 64

// stage tile loader: 128 rows x 128 bytes, SW128 xor swizzle, 128 threads
__device__ __forceinline__ void load_tile_cp(const char* __restrict__ g, uint32_t sdst, int tid)
{
#pragma unroll
    for (int j = 0; j < 8; ++j) {
        int i = tid + (j << 7);
        int r = i >> 3, seg = i & 7;
        uint32_t off = (uint32_t)((r << 7) + (((seg ^ (r & 7))) << 4));
        cp16(sdst + off, g + (size_t)r * (E_DIM * 2) + (seg << 4));
    }
}

__device__ __forceinline__ void load_stage(const char* pA, const char* pB,
                                           uint32_t su, size_t kb, int tid)
{
    load_tile_cp(pA + kb, su,          tid);
    load_tile_cp(pB + kb, su + TILE_B, tid);
    CP_COMMIT();
}

__global__ __launch_bounds__(128, 2)
void gemm_mma_fp16(const __half* __restrict__ A, const __half* __restrict__ B,
                   const float* __restrict__ bias, float* __restrict__ C,
                   int ldC, const float* __restrict__ fuseWt)
{
    extern __shared__ __align__(1024) char smem[];
    const int tid  = threadIdx.x;
    const int wid  = tid >> 5;
    const int lane = tid & 31;
    const int wm   = wid >> 1;          // 0..1
    const int wn   = wid & 1;           // 0..1
    const int m0 = blockIdx.y * 128;
    const int n0 = blockIdx.x * 128;

    const uint32_t sb = smem_u32(smem);

    const char* pA = (const char*)(A + (size_t)m0 * E_DIM);
    const char* pB = (const char*)(B + (size_t)n0 * E_DIM);

    float acc[4][8][4];
#pragma unroll
    for (int t = 0; t < 4; ++t)
#pragma unroll
        for (int j = 0; j < 8; ++j)
#pragma unroll
            for (int q = 0; q < 4; ++q) acc[t][j][q] = 0.f;

    const int rowA0 = wm * 64 + (lane & 15);                       // t adds 16
    const int rowB0 = wn * 64 + ((lane >> 4) << 3) + (lane & 7);   // pair p adds 16
    const int segA  = (lane >> 4);
    const int segB  = ((lane >> 3) & 1);

    // prologue: chunks 0,1 -> stages 0,1
    load_stage(pA, pB, sb,           0,              tid);
    load_stage(pA, pB, sb + STAGE_B, (size_t)KC * 2, tid);

    for (int c = 0; c < N_CHUNKS; ++c) {
        if (c == N_CHUNKS - 1) { CP_WAIT(0); } else { CP_WAIT(1); }
        __syncthreads();   // stage (c+2)%3 fully consumed (chunk c-1) before refill
        if (c + 2 < N_CHUNKS) {
            uint32_t su = sb + ((c + 2) % N_STAGES) * STAGE_B;
            load_stage(pA, pB, su, (size_t)(c + 2) * (KC * 2), tid);
        }

        const uint32_t su = sb + (c % N_STAGES) * STAGE_B;
#pragma unroll
        for (int ks = 0; ks < 4; ++ks) {
            uint32_t ah[4][4];
#pragma unroll
            for (int t = 0; t < 4; ++t) {
                int row = rowA0 + t * 16;
                uint32_t off = (uint32_t)(row * 128 + (((ks * 2 + segA) ^ (row & 7)) << 4));
                ldsm4(ah[t][0], ah[t][1], ah[t][2], ah[t][3], su + off);
            }
            uint32_t bh[8][2];
#pragma unroll
            for (int p = 0; p < 4; ++p) {
                int row = rowB0 + p * 16;
                uint32_t off = (uint32_t)(row * 128 + (((ks * 2 + segB) ^ (row & 7)) << 4));
                ldsm4(bh[2 * p][0], bh[2 * p][1], bh[2 * p + 1][0], bh[2 * p + 1][1],
                      su + TILE_B + off);
            }
#pragma unroll
            for (int t = 0; t < 4; ++t)
#pragma unroll
                for (int j = 0; j < 8; ++j) mma16816(acc[t][j], ah[t], bh[j]);
        }
    }

    // epilogue
    const int rbase = m0 + wm * 64 + (lane >> 2);
    const int cbase = n0 + wn * 64 + (lane & 3) * 2;
#pragma unroll
    for (int t = 0; t < 4; ++t) {
        int row0 = rbase + t * 16;
#pragma unroll
        for (int j = 0; j < 8; ++j) {
            int col = cbase + j * 8;
            float b0 = bias[col], b1 = bias[col + 1];
            float2 v0 = make_float2(acc[t][j][0] + b0, acc[t][j][1] + b1);
            float2 v1 = make_float2(acc[t][j][2] + b0, acc[t][j][3] + b1);
            if (fuseWt) {
                int h = col & 31;
                const float* w0 = fuseWt + (size_t)row0 * H_DIM;
                const float* w1 = fuseWt + (size_t)(row0 + 8) * H_DIM;
                v0.x *= w0[h]; v0.y *= w0[h + 1];
                v1.x *= w1[h]; v1.y *= w1[h + 1];
            }
            *(float2*)(C + (size_t)row0 * ldC + col)       = v0;
            *(float2*)(C + (size_t)(row0 + 8) * ldC + col) = v1;
        }
    }
}

// ---------------------------------------------------------------------------
// align + softmax weights
// ---------------------------------------------------------------------------
__global__ void attn_weights_kernel(const float* __restrict__ Q,
                                    const float* __restrict__ Kc,
                                    const int* __restrict__ mask,
                                    float* __restrict__ Wt)
{
    const int warp = threadIdx.x >> 5;
    const int h = threadIdx.x & 31;
    const int s = blockIdx.x * (blockDim.x >> 5) + warp;

    const float* q = Q + (size_t)s * E_DIM;
    const float* kc = Kc + (size_t)s * D_DIM;

    float acc = 0.f;
#pragma unroll 8
    for (int d = 0; d < D_DIM; ++d)
        acc = fmaf(kc[d], q[d * H_DIM + h], acc);

    acc *= (1.0f / 64.0f);
    if (mask[(size_t)s * H_DIM + h] == 0) acc = 1e-20f;

    float mx = acc;
#pragma unroll
    for (int o = 16; o > 0; o >>= 1) mx = fmaxf(mx, __shfl_xor_sync(0xffffffffu, mx, o));
    float e = __expf(acc - mx);
    float sum = e;
#pragma unroll
    for (int o = 16; o > 0; o >>= 1) sum += __shfl_xor_sync(0xffffffffu, sum, o);

    Wt[(size_t)s * H_DIM + h] = e / sum;
}

// ---------------------------------------------------------------------------
// Launch
// ---------------------------------------------------------------------------
extern "C" void kernel_launch(void* const* d_in, const int* in_sizes, int n_in,
                              void* d_out, int out_size)
{
    (void)in_sizes; (void)n_in; (void)out_size;

    const float* x    = (const float*)d_in[0];
    const float* Wq   = (const float*)d_in[1];
    const float* bq   = (const float*)d_in[2];
    const float* Wk   = (const float*)d_in[3];
    const float* bk   = (const float*)d_in[4];
    const float* Wv   = (const float*)d_in[5];
    const float* bv   = (const float*)d_in[6];
    const int*   mask = (const int*)d_in[7];
    float* out = (float*)d_out;

    __half *xh, *wq, *wv, *wk;
    float *bkc, *Qp, *Kcp, *Wtp;
    cudaGetSymbolAddress((void**)&xh, g_x);
    cudaGetSymbolAddress((void**)&wq, g_wq);
    cudaGetSymbolAddress((void**)&wv, g_wv);
    cudaGetSymbolAddress((void**)&wk, g_wk);
    cudaGetSymbolAddress((void**)&bkc, g_bkc);
    cudaGetSymbolAddress((void**)&Qp, g_Q);
    cudaGetSymbolAddress((void**)&Kcp, g_Kc);
    cudaGetSymbolAddress((void**)&Wtp, g_Wt);

    cudaFuncSetAttribute(gemm_mma_fp16, cudaFuncAttributeMaxDynamicSharedMemorySize, SMEM_TOTAL);

    // conversions
    int n4x = (S_DIM * E_DIM) / 4;
    cvt_kernel<<<n4x / 256, 256>>>((const float4*)x, (__half2*)xh, n4x);
    int n4w = (E_DIM * E_DIM) / 4;
    cvt_kernel<<<n4w / 256, 256>>>((const float4*)Wq, (__half2*)wq, n4w);
    cvt_kernel<<<n4w / 256, 256>>>((const float4*)Wv, (__half2*)wv, n4w);
    gather_wk_kernel<<<(D_DIM * E_DIM / 4) / 256, 256>>>(Wk, bk, wk, bkc);

    // Q = x @ Wq.T + bq
    gemm_mma_fp16<<<dim3(E_DIM / 128, S_DIM / 128), 128, SMEM_TOTAL>>>(xh, wq, bq, Qp, E_DIM, nullptr);
    // Kc = x @ Wk_sub.T + bk_sub
    gemm_mma_fp16<<<dim3(1, S_DIM / 128), 128, SMEM_TOTAL>>>(xh, wk, bkc, Kcp, D_DIM, nullptr);
    // softmax weights
    attn_weights_kernel<<<S_DIM / 4, 128>>>(Qp, Kcp, mask, Wtp);
    // out = (x @ Wv.T + bv) * weights (fused epilogue)
    gemm_mma_fp16<<<dim3(E_DIM / 128, S_DIM / 128), 128, SMEM_TOTAL>>>(xh, wv, bv, out, E_DIM, Wtp);
}